// round 5
// baseline (speedup 1.0000x reference)
#include <cuda_runtime.h>

#define N_MAX 100000
#define TPB 256

// Scratch (allocation-free rule: __device__ globals)
__device__ int    g_deg[N_MAX];
__device__ float  g_dinv[N_MAX];
__device__ float4 g_agg4[N_MAX];   // layer-1 aggregation, features 0..3 (16B aligned for RED.v4)
__device__ float  g_agg5[N_MAX];   // layer-1 aggregation, feature 4
__device__ float  g_z[N_MAX];      // per-node scalar after layer-2 linear

__device__ __forceinline__ void red_add_v4(float4* addr, float4 v) {
    asm volatile("red.global.add.v4.f32 [%0], {%1, %2, %3, %4};"
                 :: "l"(addr), "f"(v.x), "f"(v.y), "f"(v.z), "f"(v.w)
                 : "memory");
}

__global__ void k_init(int n) {
    int i = blockIdx.x * blockDim.x + threadIdx.x;
    if (i < n) {
        g_agg4[i] = make_float4(0.f, 0.f, 0.f, 0.f);
        g_agg5[i] = 0.f;
        g_deg[i]  = 1;              // self-loop contributes 1 to degree
    }
}

__global__ void k_degree(const int* __restrict__ dst, int E) {
    int e = blockIdx.x * blockDim.x + threadIdx.x;
    if (e >= E) return;
    int d = __ldcs(dst + e);
    atomicAdd(&g_deg[d], 1);        // result unused -> RED
}

__global__ void k_dinv(int n) {
    int i = blockIdx.x * blockDim.x + threadIdx.x;
    if (i < n) g_dinv[i] = rsqrtf((float)g_deg[i]);
}

__global__ void k_agg1(const int* __restrict__ ei,
                       const float* __restrict__ x, int E) {
    int e = blockIdx.x * blockDim.x + threadIdx.x;
    if (e >= E) return;
    int s = __ldcs(ei + e);          // src
    int d = __ldcs(ei + E + e);      // dst
    float norm = g_dinv[s] * g_dinv[d];
    const float* xs = x + (long)s * 5;
    float4 v = make_float4(xs[0] * norm, xs[1] * norm, xs[2] * norm, xs[3] * norm);
    red_add_v4(&g_agg4[d], v);                 // HW RED.v4.f32
    atomicAdd(&g_agg5[d], xs[4] * norm);
}

// Per-node: self-loop term, 5->16 GEMM + bias + relu, 16->1 GEMM -> z.
// Seeds out[i] with the self-loop + bias part of layer 2.
__global__ void k_node(const float* __restrict__ x,
                       const float* __restrict__ W1, const float* __restrict__ b1,
                       const float* __restrict__ W2, const float* __restrict__ b2,
                       float* __restrict__ out, int n) {
    __shared__ float sW1[80];
    __shared__ float sb1[16];
    __shared__ float sW2[16];
    __shared__ float sb2;
    int t = threadIdx.x;
    if (t < 80) sW1[t] = W1[t];
    if (t < 16) { sb1[t] = b1[t]; sW2[t] = W2[t]; }
    if (t == 0) sb2 = b2[0];
    __syncthreads();

    int i = blockIdx.x * blockDim.x + t;
    if (i >= n) return;

    float di = g_dinv[i];
    float sl = di * di;             // self-loop norm = dinv[i]^2

    float4 p0 = g_agg4[i];
    float a[5] = {p0.x, p0.y, p0.z, p0.w, g_agg5[i]};
    const float* xi = x + (long)i * 5;
    #pragma unroll
    for (int k = 0; k < 5; k++) a[k] = fmaf(xi[k], sl, a[k]);

    float z = 0.0f;
    #pragma unroll
    for (int j = 0; j < 16; j++) {
        float h = sb1[j];
        #pragma unroll
        for (int k = 0; k < 5; k++) h = fmaf(a[k], sW1[k * 16 + j], h);
        h = fmaxf(h, 0.0f);         // relu
        z = fmaf(h, sW2[j], z);
    }
    g_z[i] = z;
    out[i] = z * sl + sb2;          // layer-2 self-loop + bias
}

__global__ void k_agg2(const int* __restrict__ ei,
                       float* __restrict__ out, int E) {
    int e = blockIdx.x * blockDim.x + threadIdx.x;
    if (e >= E) return;
    int s = __ldcs(ei + e);
    int d = __ldcs(ei + E + e);
    atomicAdd(&out[d], g_z[s] * g_dinv[s] * g_dinv[d]);
}

extern "C" void kernel_launch(void* const* d_in, const int* in_sizes, int n_in,
                              void* d_out, int out_size) {
    const float* x  = (const float*)d_in[0];
    const int*   ei = (const int*)d_in[1];   // int32: JAX x64-disabled canonicalizes int64 -> int32
    const float* W1 = (const float*)d_in[2];
    const float* b1 = (const float*)d_in[3];
    const float* W2 = (const float*)d_in[4];
    const float* b2 = (const float*)d_in[5];
    float* out = (float*)d_out;

    int n = in_sizes[0] / 5;
    int E = in_sizes[1] / 2;

    int gb_e = (E + TPB - 1) / TPB;
    int gb_n = (n + TPB - 1) / TPB;

    k_init  <<<gb_n, TPB>>>(n);
    k_degree<<<gb_e, TPB>>>(ei + E, E);
    k_dinv  <<<gb_n, TPB>>>(n);
    k_agg1  <<<gb_e, TPB>>>(ei, x, E);
    k_node  <<<gb_n, TPB>>>(x, W1, b1, W2, b2, out, n);
    k_agg2  <<<gb_e, TPB>>>(ei, out, E);
}

// round 6
// speedup vs baseline: 1.2831x; 1.2831x over previous
#include <cuda_runtime.h>

#define N_MAX 100000
#define TPB 256

// Scratch (allocation-free rule: __device__ globals)
__device__ int    g_deg[N_MAX];
__device__ float  g_dinv[N_MAX];
__device__ float4 g_y4[N_MAX];     // pre-scaled features 0..3: x*dinv
__device__ float  g_y5[N_MAX];     // pre-scaled feature 4
__device__ float4 g_agg4[N_MAX];   // layer-1 aggregation (16B aligned for RED.v4)
__device__ float  g_agg5[N_MAX];
__device__ float  g_zs[N_MAX];     // layer-2 per-node scalar, pre-scaled by dinv
__device__ float  g_a2[N_MAX];     // layer-2 aggregation

__device__ __forceinline__ void red_add_v4(float4* addr, float4 v) {
    asm volatile("red.global.add.v4.f32 [%0], {%1, %2, %3, %4};"
                 :: "l"(addr), "f"(v.x), "f"(v.y), "f"(v.z), "f"(v.w)
                 : "memory");
}

__global__ void k_init(int n) {
    int i = blockIdx.x * blockDim.x + threadIdx.x;
    if (i < n) g_deg[i] = 1;        // self-loop contributes 1 to degree
}

__global__ void k_degree(const int* __restrict__ dst, int E) {
    int e = blockIdx.x * blockDim.x + threadIdx.x;
    if (e >= E) return;
    atomicAdd(&g_deg[__ldcs(dst + e)], 1);   // result unused -> RED
}

// dinv, pre-scaled features, and seed layer-1 agg with the self-loop term:
// self contribution to node i = dinv_i^2 * x_i = dinv_i * y_i  (dinv_i applied later)
__global__ void k_prep(const float* __restrict__ x, int n) {
    int i = blockIdx.x * blockDim.x + threadIdx.x;
    if (i >= n) return;
    float di = rsqrtf((float)g_deg[i]);
    g_dinv[i] = di;
    const float* xi = x + (long)i * 5;
    float4 y = make_float4(xi[0] * di, xi[1] * di, xi[2] * di, xi[3] * di);
    float y5 = xi[4] * di;
    g_y4[i] = y;  g_y5[i] = y5;
    g_agg4[i] = y;  g_agg5[i] = y5;   // seed = self-loop
}

__global__ void k_agg1(const int* __restrict__ ei, int E) {
    int e = blockIdx.x * blockDim.x + threadIdx.x;
    if (e >= E) return;
    int s = __ldcs(ei + e);          // src
    int d = __ldcs(ei + E + e);      // dst
    red_add_v4(&g_agg4[d], g_y4[s]); // HW RED.v4.f32
    atomicAdd(&g_agg5[d], g_y5[s]);
}

// Per-node: finish layer-1 norm (×dinv), 5->16 GEMM + bias + relu, 16->1 GEMM.
// Emits zs = z*dinv and seeds layer-2 agg with the self-loop term (= zs).
__global__ void k_node(const float* __restrict__ W1, const float* __restrict__ b1,
                       const float* __restrict__ W2, int n) {
    __shared__ float sW1[80];
    __shared__ float sb1[16];
    __shared__ float sW2[16];
    int t = threadIdx.x;
    if (t < 80) sW1[t] = W1[t];
    if (t < 16) { sb1[t] = b1[t]; sW2[t] = W2[t]; }
    __syncthreads();

    int i = blockIdx.x * blockDim.x + t;
    if (i >= n) return;

    float di = g_dinv[i];
    float4 p = g_agg4[i];
    float a[5] = {p.x * di, p.y * di, p.z * di, p.w * di, g_agg5[i] * di};

    float z = 0.0f;
    #pragma unroll
    for (int j = 0; j < 16; j++) {
        float h = sb1[j];
        #pragma unroll
        for (int k = 0; k < 5; k++) h = fmaf(a[k], sW1[k * 16 + j], h);
        h = fmaxf(h, 0.0f);          // relu
        z = fmaf(h, sW2[j], z);
    }
    float zs = z * di;
    g_zs[i] = zs;
    g_a2[i] = zs;                    // seed = self-loop (dinv^2*z = dinv * zs)
}

__global__ void k_agg2(const int* __restrict__ ei, int E) {
    int e = blockIdx.x * blockDim.x + threadIdx.x;
    if (e >= E) return;
    int s = __ldcs(ei + e);
    int d = __ldcs(ei + E + e);
    atomicAdd(&g_a2[d], g_zs[s]);
}

__global__ void k_out(const float* __restrict__ b2, float* __restrict__ out, int n) {
    int i = blockIdx.x * blockDim.x + threadIdx.x;
    if (i < n) out[i] = g_a2[i] * g_dinv[i] + b2[0];
}

extern "C" void kernel_launch(void* const* d_in, const int* in_sizes, int n_in,
                              void* d_out, int out_size) {
    const float* x  = (const float*)d_in[0];
    const int*   ei = (const int*)d_in[1];   // int32 (JAX x64-disabled canonicalizes int64)
    const float* W1 = (const float*)d_in[2];
    const float* b1 = (const float*)d_in[3];
    const float* W2 = (const float*)d_in[4];
    const float* b2 = (const float*)d_in[5];
    float* out = (float*)d_out;

    int n = in_sizes[0] / 5;
    int E = in_sizes[1] / 2;

    int gb_e = (E + TPB - 1) / TPB;
    int gb_n = (n + TPB - 1) / TPB;

    k_init  <<<gb_n, TPB>>>(n);
    k_degree<<<gb_e, TPB>>>(ei + E, E);
    k_prep  <<<gb_n, TPB>>>(x, n);
    k_agg1  <<<gb_e, TPB>>>(ei, E);
    k_node  <<<gb_n, TPB>>>(W1, b1, W2, n);
    k_agg2  <<<gb_e, TPB>>>(ei, E);
    k_out   <<<gb_n, TPB>>>(b2, out, n);
}

// round 7
// speedup vs baseline: 1.4572x; 1.1357x over previous
#include <cuda_runtime.h>

#define N_MAX 100000
#define TPB 256

// Scratch (allocation-free rule: __device__ globals).
// 32B rows: slots 0..4 = features, 5..7 stay zero (zero-init, never written).
__device__ __align__(32) float g_y8[N_MAX][8];    // pre-scaled features x*dinv
__device__ __align__(32) float g_agg8[N_MAX][8];  // layer-1 aggregation
__device__ int   g_deg[N_MAX];                    // zero at entry of every call (restored in k_out)
__device__ float g_dinv[N_MAX];
__device__ float g_zs[N_MAX];                     // layer-2 per-node scalar, pre-scaled by dinv
__device__ float g_a2[N_MAX];                     // layer-2 aggregation

__device__ __forceinline__ void red_add_v4(float* addr, float a, float b, float c, float d) {
    asm volatile("red.global.add.v4.f32 [%0], {%1, %2, %3, %4};"
                 :: "l"(addr), "f"(a), "f"(b), "f"(c), "f"(d) : "memory");
}

// Blackwell (sm_100a) 256-bit load: one L1 wavefront for a full 8-float row.
__device__ __forceinline__ void ld_v8(const float* p, float r[8]) {
    asm("ld.global.v8.f32 {%0,%1,%2,%3,%4,%5,%6,%7}, [%8];"
        : "=f"(r[0]), "=f"(r[1]), "=f"(r[2]), "=f"(r[3]),
          "=f"(r[4]), "=f"(r[5]), "=f"(r[6]), "=f"(r[7])
        : "l"(p));
}

// Degree: 4 edges per thread, int4 index loads. g_deg starts at 0; +1 self-loop
// is folded into k_prep's rsqrt(deg+1).
__global__ void k_degree(const int* __restrict__ dst, int E) {
    int i = blockIdx.x * blockDim.x + threadIdx.x;
    int e0 = i * 4;
    if (e0 + 3 < E) {
        int4 d = *reinterpret_cast<const int4*>(dst + e0);
        atomicAdd(&g_deg[d.x], 1);
        atomicAdd(&g_deg[d.y], 1);
        atomicAdd(&g_deg[d.z], 1);
        atomicAdd(&g_deg[d.w], 1);
    } else {
        for (int e = e0; e < E; e++) atomicAdd(&g_deg[dst[e]], 1);
    }
}

// dinv, pre-scaled features, and seed layer-1 agg with the self-loop term.
__global__ void k_prep(const float* __restrict__ x, int n) {
    int i = blockIdx.x * blockDim.x + threadIdx.x;
    if (i >= n) return;
    float di = rsqrtf((float)(g_deg[i] + 1));   // +1 = self-loop
    g_dinv[i] = di;
    const float* xi = x + (long)i * 5;
    float4 y = make_float4(xi[0] * di, xi[1] * di, xi[2] * di, xi[3] * di);
    float y5 = xi[4] * di;
    *reinterpret_cast<float4*>(&g_y8[i][0]) = y;   g_y8[i][4] = y5;
    *reinterpret_cast<float4*>(&g_agg8[i][0]) = y; g_agg8[i][4] = y5;  // seed = self-loop
}

__global__ void k_agg1(const int* __restrict__ ei, int E) {
    int e = blockIdx.x * blockDim.x + threadIdx.x;
    if (e >= E) return;
    int s = __ldcs(ei + e);          // src
    int d = __ldcs(ei + E + e);      // dst
    float r[8];
    ld_v8(&g_y8[s][0], r);                             // 1 wavefront
    red_add_v4(&g_agg8[d][0], r[0], r[1], r[2], r[3]); // 1 wavefront
    atomicAdd(&g_agg8[d][4], r[4]);                    // 1 wavefront
}

// Per-node: finish layer-1 norm (x dinv), 5->16 GEMM + bias + relu, 16->1 GEMM.
// Emits zs = z*dinv and seeds layer-2 agg with the self-loop term.
__global__ void k_node(const float* __restrict__ W1, const float* __restrict__ b1,
                       const float* __restrict__ W2, int n) {
    __shared__ float sW1[80];
    __shared__ float sb1[16];
    __shared__ float sW2[16];
    int t = threadIdx.x;
    if (t < 80) sW1[t] = W1[t];
    if (t < 16) { sb1[t] = b1[t]; sW2[t] = W2[t]; }
    __syncthreads();

    int i = blockIdx.x * blockDim.x + t;
    if (i >= n) return;

    float di = g_dinv[i];
    float r[8];
    ld_v8(&g_agg8[i][0], r);
    float a[5] = {r[0] * di, r[1] * di, r[2] * di, r[3] * di, r[4] * di};

    float z = 0.0f;
    #pragma unroll
    for (int j = 0; j < 16; j++) {
        float h = sb1[j];
        #pragma unroll
        for (int k = 0; k < 5; k++) h = fmaf(a[k], sW1[k * 16 + j], h);
        h = fmaxf(h, 0.0f);          // relu
        z = fmaf(h, sW2[j], z);
    }
    float zs = z * di;
    g_zs[i] = zs;
    g_a2[i] = zs;                    // seed = self-loop
}

__global__ void k_agg2(const int* __restrict__ ei, int E) {
    int e = blockIdx.x * blockDim.x + threadIdx.x;
    if (e >= E) return;
    int s = __ldcs(ei + e);
    int d = __ldcs(ei + E + e);
    atomicAdd(&g_a2[d], g_zs[s]);
}

// Final output; also restores g_deg = 0 so every kernel_launch call sees the
// same initial state (determinism across graph replays).
__global__ void k_out(const float* __restrict__ b2, float* __restrict__ out, int n) {
    int i = blockIdx.x * blockDim.x + threadIdx.x;
    if (i < n) {
        out[i] = g_a2[i] * g_dinv[i] + b2[0];
        g_deg[i] = 0;
    }
}

extern "C" void kernel_launch(void* const* d_in, const int* in_sizes, int n_in,
                              void* d_out, int out_size) {
    const float* x  = (const float*)d_in[0];
    const int*   ei = (const int*)d_in[1];   // int32 (JAX x64-disabled canonicalizes int64)
    const float* W1 = (const float*)d_in[2];
    const float* b1 = (const float*)d_in[3];
    const float* W2 = (const float*)d_in[4];
    const float* b2 = (const float*)d_in[5];
    float* out = (float*)d_out;

    int n = in_sizes[0] / 5;
    int E = in_sizes[1] / 2;

    int gb_e  = (E + TPB - 1) / TPB;
    int gb_e4 = ((E + 3) / 4 + TPB - 1) / TPB;
    int gb_n  = (n + TPB - 1) / TPB;

    k_degree<<<gb_e4, TPB>>>(ei + E, E);
    k_prep  <<<gb_n,  TPB>>>(x, n);
    k_agg1  <<<gb_e,  TPB>>>(ei, E);
    k_node  <<<gb_n,  TPB>>>(W1, b1, W2, n);
    k_agg2  <<<gb_e,  TPB>>>(ei, E);
    k_out   <<<gb_n,  TPB>>>(b2, out, n);
}

// round 10
// speedup vs baseline: 1.6266x; 1.1162x over previous
#include <cuda_runtime.h>
#include <cuda_fp16.h>

#define N_MAX 100000
#define TPB 256
#define TPB_N 128

// Scratch (allocation-free rule: __device__ globals).
// fp16 rows of 8 (16B): slots 0..4 = features, 5..7 stay zero.
__device__ __align__(16) __half g_yh[N_MAX][8];    // pre-scaled features x*dinv (fp16)
__device__ __align__(16) __half g_aggh[N_MAX][8];  // layer-1 aggregation (fp16)
__device__ int   g_deg[N_MAX];                     // zero at entry (restored in k_out)
__device__ float g_dinv[N_MAX];
__device__ float g_zs[N_MAX];                      // layer-2 per-node scalar, pre-scaled by dinv
__device__ float g_a2[N_MAX];                      // layer-2 aggregation

__device__ __forceinline__ unsigned h2_bits(__half2 h) {
    return *reinterpret_cast<unsigned*>(&h);
}

// One 128-bit vector half-precision reduction: 8 halves in a single op.
__device__ __forceinline__ void red_add_v4_f16x2(void* addr, uint4 w) {
    asm volatile("red.global.add.noftz.v4.f16x2 [%0], {%1, %2, %3, %4};"
                 :: "l"(addr), "r"(w.x), "r"(w.y), "r"(w.z), "r"(w.w) : "memory");
}

// Degree: 4 edges per thread, int4 index loads. +1 self-loop folded into k_prep.
__global__ void k_degree(const int* __restrict__ dst, int E) {
    int i = blockIdx.x * blockDim.x + threadIdx.x;
    int e0 = i * 4;
    if (e0 + 3 < E) {
        int4 d = *reinterpret_cast<const int4*>(dst + e0);
        atomicAdd(&g_deg[d.x], 1);
        atomicAdd(&g_deg[d.y], 1);
        atomicAdd(&g_deg[d.z], 1);
        atomicAdd(&g_deg[d.w], 1);
    } else {
        for (int e = e0; e < E; e++) atomicAdd(&g_deg[dst[e]], 1);
    }
}

// dinv, pre-scaled fp16 features, seed layer-1 agg with the self-loop term.
__global__ void k_prep(const float* __restrict__ x, int n) {
    int i = blockIdx.x * blockDim.x + threadIdx.x;
    if (i >= n) return;
    float di = rsqrtf((float)(g_deg[i] + 1));   // +1 = self-loop
    g_dinv[i] = di;
    const float* xi = x + (long)i * 5;
    __half2 p0 = __floats2half2_rn(xi[0] * di, xi[1] * di);
    __half2 p1 = __floats2half2_rn(xi[2] * di, xi[3] * di);
    __half2 p2 = __floats2half2_rn(xi[4] * di, 0.f);
    uint4 w = make_uint4(h2_bits(p0), h2_bits(p1), h2_bits(p2), 0u);
    *reinterpret_cast<uint4*>(&g_yh[i][0])   = w;
    *reinterpret_cast<uint4*>(&g_aggh[i][0]) = w;   // seed = self-loop
}

__global__ void k_agg1(const int* __restrict__ ei, int E) {
    int e = blockIdx.x * blockDim.x + threadIdx.x;
    if (e >= E) return;
    int s = __ldcs(ei + e);          // src
    int d = __ldcs(ei + E + e);      // dst
    uint4 w = *reinterpret_cast<const uint4*>(&g_yh[s][0]);  // 16B gather, 1 wavefront
    red_add_v4_f16x2(&g_aggh[d][0], w);                      // 1 RED, 4 LTS lanes
}

// Per-node: finish layer-1 norm (x dinv), 5->16 GEMM + bias + relu, 16->1 GEMM.
// Emits zs = z*dinv and seeds layer-2 agg with the self-loop term.
__global__ void k_node(const float* __restrict__ W1, const float* __restrict__ b1,
                       const float* __restrict__ W2, int n) {
    __shared__ float sW1[80];
    __shared__ float sb1[16];
    __shared__ float sW2[16];
    int t = threadIdx.x;
    if (t < 80) sW1[t] = W1[t];
    if (t < 16) { sb1[t] = b1[t]; sW2[t] = W2[t]; }
    __syncthreads();

    int i = blockIdx.x * blockDim.x + t;
    if (i >= n) return;

    float di = g_dinv[i];
    const __half2* hp = reinterpret_cast<const __half2*>(&g_aggh[i][0]);
    float2 f0 = __half22float2(hp[0]);
    float2 f1 = __half22float2(hp[1]);
    float2 f2 = __half22float2(hp[2]);
    float a[5] = {f0.x * di, f0.y * di, f1.x * di, f1.y * di, f2.x * di};

    float z = 0.0f;
    #pragma unroll
    for (int j = 0; j < 16; j++) {
        float h = sb1[j];
        #pragma unroll
        for (int k = 0; k < 5; k++) h = fmaf(a[k], sW1[k * 16 + j], h);
        h = fmaxf(h, 0.0f);          // relu
        z = fmaf(h, sW2[j], z);
    }
    float zs = z * di;
    g_zs[i] = zs;
    g_a2[i] = zs;                    // seed = self-loop
}

__global__ void k_agg2(const int* __restrict__ ei, int E) {
    int e = blockIdx.x * blockDim.x + threadIdx.x;
    if (e >= E) return;
    int s = __ldcs(ei + e);
    int d = __ldcs(ei + E + e);
    atomicAdd(&g_a2[d], g_zs[s]);
}

// Final output; restores g_deg = 0 so every launch sees identical initial state.
__global__ void k_out(const float* __restrict__ b2, float* __restrict__ out, int n) {
    int i = blockIdx.x * blockDim.x + threadIdx.x;
    if (i < n) {
        out[i] = g_a2[i] * g_dinv[i] + b2[0];
        g_deg[i] = 0;
    }
}

extern "C" void kernel_launch(void* const* d_in, const int* in_sizes, int n_in,
                              void* d_out, int out_size) {
    const float* x  = (const float*)d_in[0];
    const int*   ei = (const int*)d_in[1];   // int32 (JAX x64-disabled canonicalizes int64)
    const float* W1 = (const float*)d_in[2];
    const float* b1 = (const float*)d_in[3];
    const float* W2 = (const float*)d_in[4];
    const float* b2 = (const float*)d_in[5];
    float* out = (float*)d_out;

    int n = in_sizes[0] / 5;
    int E = in_sizes[1] / 2;

    int gb_e  = (E + TPB - 1) / TPB;
    int gb_e4 = ((E + 3) / 4 + TPB - 1) / TPB;
    int gb_n  = (n + TPB - 1) / TPB;
    int gb_nn = (n + TPB_N - 1) / TPB_N;

    k_degree<<<gb_e4, TPB>>>(ei + E, E);
    k_prep  <<<gb_n,  TPB>>>(x, n);
    k_agg1  <<<gb_e,  TPB>>>(ei, E);
    k_node  <<<gb_nn, TPB_N>>>(W1, b1, W2, n);
    k_agg2  <<<gb_e,  TPB>>>(ei, E);
    k_out   <<<gb_n,  TPB>>>(b2, out, n);
}